// round 10
// baseline (speedup 1.0000x reference)
#include <cuda_runtime.h>
#include <cuda_fp16.h>
#include <cstdint>

#define NNODES 100000
#define NEDGES 1600000
#define FIN    128
#define HID    64
#define NCLS   40

#define SCAN_BLOCKS 98   // 98 * 1024 >= NNODES

// ---------------- device scratch (allocation-free) ----------------
__device__ int    g_hist[NNODES];
__device__ int    g_cnt[NNODES];
__device__ int    g_offs[NNODES];          // block-local exclusive offsets
__device__ int    g_bsum[SCAN_BLOCKS];
__device__ int    g_boff[SCAN_BLOCKS];     // global block offsets (exclusive)
__device__ int    g_csr_src[NEDGES];
__device__ float  g_dinv[NNODES];
__device__ __half g_h1h[(size_t)NNODES * HID];    // (x @ W1) * dinv[row], fp16
__device__ float  g_agg1[(size_t)NNODES * HID];   // fp32
__device__ __half g_h2h[(size_t)NNODES * NCLS];   // (relu(agg1) @ W2) * dinv[row], fp16

// ---------------- helpers ----------------
typedef unsigned long long u64;
__device__ __forceinline__ u64 ffma2(u64 a, u64 b, u64 c) {
    u64 d;
    asm("fma.rn.f32x2 %0, %1, %2, %3;" : "=l"(d) : "l"(a), "l"(b), "l"(c));
    return d;
}
__device__ __forceinline__ u64 pack2(float x) {
    u64 d;
    asm("mov.b64 %0, {%1, %1};" : "=l"(d) : "f"(x));
    return d;
}
union F2 { u64 u; float2 f; };
union W4 { float4 v; struct { u64 lo, hi; } u; };

__device__ __forceinline__ float2 h2tof2(uint32_t h) {
    __half2 hh = *reinterpret_cast<__half2*>(&h);
    return __half22float2(hh);
}

// global CSR range for node n
__device__ __forceinline__ void node_range(int n, int& p0, int& p1) {
    p0 = g_offs[n] + g_boff[n >> 10];
    int m = n + 1;
    p1 = (m == NNODES) ? NEDGES : (g_offs[m] + g_boff[m >> 10]);
}

// ---------------- CSR build ----------------
__global__ void k_zero() {
    int i = blockIdx.x * blockDim.x + threadIdx.x;
    if (i < NNODES) g_hist[i] = 0;
}
__global__ void k_hist(const int* __restrict__ dst) {
    int e = blockIdx.x * blockDim.x + threadIdx.x;
    if (e < NEDGES) atomicAdd(&g_hist[dst[e]], 1);
}
__global__ void __launch_bounds__(1024) k_scan1() {
    __shared__ int sh[1024];
    int i = blockIdx.x * 1024 + threadIdx.x;
    int h = (i < NNODES) ? g_hist[i] : 0;
    sh[threadIdx.x] = h;
    __syncthreads();
    #pragma unroll
    for (int ofs = 1; ofs < 1024; ofs <<= 1) {
        int v = (threadIdx.x >= ofs) ? sh[threadIdx.x - ofs] : 0;
        __syncthreads();
        sh[threadIdx.x] += v;
        __syncthreads();
    }
    if (i < NNODES) {
        g_offs[i] = sh[threadIdx.x] - h;
        g_dinv[i] = rsqrtf((float)(h + 1));
        g_cnt[i]  = 0;
    }
    if (threadIdx.x == 1023) g_bsum[blockIdx.x] = sh[1023];
}
__global__ void __launch_bounds__(128) k_scan2() {
    __shared__ int sh[128];
    int t = threadIdx.x;
    int v = (t < SCAN_BLOCKS) ? g_bsum[t] : 0;
    sh[t] = v;
    __syncthreads();
    #pragma unroll
    for (int ofs = 1; ofs < 128; ofs <<= 1) {
        int u = (t >= ofs) ? sh[t - ofs] : 0;
        __syncthreads();
        sh[t] += u;
        __syncthreads();
    }
    if (t < SCAN_BLOCKS) g_boff[t] = sh[t] - v;
}
__global__ void k_fill(const int* __restrict__ src, const int* __restrict__ dst) {
    int e = blockIdx.x * blockDim.x + threadIdx.x;
    if (e >= NEDGES) return;
    int s = src[e], d = dst[e];
    int pos = g_offs[d] + g_boff[d >> 10] + atomicAdd(&g_cnt[d], 1);
    g_csr_src[pos] = s;
}

// ---------------- GEMM1: h1h = (x @ W1) * dinv  (fp16 out) ----------------
#define XS_PITCH 132
__global__ void __launch_bounds__(128, 2) k_gemm1(const float* __restrict__ x,
                                                  const float* __restrict__ W1) {
    __shared__ float xs[128 * XS_PITCH];  // 67.6 KB
    __shared__ float ws[FIN * HID];       // 32 KB
    const int tid  = threadIdx.x;
    const int row0 = blockIdx.x * 128;

    {
        const float4* wsrc = (const float4*)W1;
        float4* wdst = (float4*)ws;
        #pragma unroll
        for (int i = 0; i < 16; i++) wdst[tid + i * 128] = wsrc[tid + i * 128];
    }
    {
        #pragma unroll
        for (int i = 0; i < 32; i++) {
            int f = tid + i * 128;
            int r = f >> 5;
            int o = (f & 31) << 2;
            float4 v = make_float4(0.f, 0.f, 0.f, 0.f);
            if (row0 + r < NNODES) v = *(const float4*)(x + (size_t)(row0 + r) * FIN + o);
            *(float4*)(xs + r * XS_PITCH + o) = v;
        }
    }
    __syncthreads();

    const int rp = tid >> 3;
    const int cg = tid & 7;
    const float* wcol = ws + cg * 8;
    const float* xr = xs + (rp * 8) * XS_PITCH;

    u64 acc[8][4];
    #pragma unroll
    for (int r = 0; r < 8; r++)
        #pragma unroll
        for (int j = 0; j < 4; j++) acc[r][j] = 0ull;

    #pragma unroll 2
    for (int k = 0; k < FIN; k += 4) {
        float4 xa[8];
        #pragma unroll
        for (int r = 0; r < 8; r++)
            xa[r] = *(const float4*)(xr + r * XS_PITCH + k);
        #pragma unroll
        for (int kk = 0; kk < 4; kk++) {
            W4 w0, w1;
            w0.v = *(const float4*)(wcol + (k + kk) * HID);
            w1.v = *(const float4*)(wcol + (k + kk) * HID + 4);
            #pragma unroll
            for (int r = 0; r < 8; r++) {
                u64 xv = pack2((&xa[r].x)[kk]);
                acc[r][0] = ffma2(w0.u.lo, xv, acc[r][0]);
                acc[r][1] = ffma2(w0.u.hi, xv, acc[r][1]);
                acc[r][2] = ffma2(w1.u.lo, xv, acc[r][2]);
                acc[r][3] = ffma2(w1.u.hi, xv, acc[r][3]);
            }
        }
    }

    #pragma unroll
    for (int r = 0; r < 8; r++) {
        int row = row0 + rp * 8 + r;
        if (row >= NNODES) continue;
        float di = g_dinv[row];
        F2 a0, a1, a2, a3;
        a0.u = acc[r][0]; a1.u = acc[r][1]; a2.u = acc[r][2]; a3.u = acc[r][3];
        uint4 st;
        __half2* sp = (__half2*)&st;
        sp[0] = __floats2half2_rn(a0.f.x * di, a0.f.y * di);
        sp[1] = __floats2half2_rn(a1.f.x * di, a1.f.y * di);
        sp[2] = __floats2half2_rn(a2.f.x * di, a2.f.y * di);
        sp[3] = __floats2half2_rn(a3.f.x * di, a3.f.y * di);
        *(uint4*)(g_h1h + (size_t)row * HID + cg * 8) = st;
    }
}

// ---------------- agg1: agg1[n] = (h1h[n] + sum h1h[src]) * dinv[n] + b1 ----------------
// 8 lanes per node; lane j owns 8 halves (16B).
__global__ void __launch_bounds__(256) k_agg1(const float* __restrict__ b1) {
    int t = blockIdx.x * 256 + threadIdx.x;
    int n = t >> 3;
    if (n >= NNODES) return;
    int j = t & 7;

    int p0, p1;
    node_range(n, p0, p1);

    float acc[8];
    {   // self-loop seed
        uint4 v = *(const uint4*)(g_h1h + (size_t)n * HID + j * 8);
        float2 f0 = h2tof2(v.x), f1 = h2tof2(v.y), f2 = h2tof2(v.z), f3 = h2tof2(v.w);
        acc[0] = f0.x; acc[1] = f0.y; acc[2] = f1.x; acc[3] = f1.y;
        acc[4] = f2.x; acc[5] = f2.y; acc[6] = f3.x; acc[7] = f3.y;
    }
    int p = p0;
    for (; p + 8 <= p1; p += 8) {
        int s[8];
        #pragma unroll
        for (int q = 0; q < 8; q++) s[q] = g_csr_src[p + q];
        uint4 v[8];
        #pragma unroll
        for (int q = 0; q < 8; q++)
            v[q] = *(const uint4*)(g_h1h + (size_t)s[q] * HID + j * 8);
        #pragma unroll
        for (int q = 0; q < 8; q++) {
            float2 f0 = h2tof2(v[q].x), f1 = h2tof2(v[q].y);
            float2 f2 = h2tof2(v[q].z), f3 = h2tof2(v[q].w);
            acc[0] += f0.x; acc[1] += f0.y; acc[2] += f1.x; acc[3] += f1.y;
            acc[4] += f2.x; acc[5] += f2.y; acc[6] += f3.x; acc[7] += f3.y;
        }
    }
    for (; p < p1; p++) {
        int s = g_csr_src[p];
        uint4 v = *(const uint4*)(g_h1h + (size_t)s * HID + j * 8);
        float2 f0 = h2tof2(v.x), f1 = h2tof2(v.y), f2 = h2tof2(v.z), f3 = h2tof2(v.w);
        acc[0] += f0.x; acc[1] += f0.y; acc[2] += f1.x; acc[3] += f1.y;
        acc[4] += f2.x; acc[5] += f2.y; acc[6] += f3.x; acc[7] += f3.y;
    }
    float di = g_dinv[n];
    float4 bb0 = *(const float4*)(b1 + j * 8);
    float4 bb1 = *(const float4*)(b1 + j * 8 + 4);
    float* ap = g_agg1 + (size_t)n * HID + j * 8;
    *(float4*)(ap)     = make_float4(fmaf(acc[0], di, bb0.x), fmaf(acc[1], di, bb0.y),
                                     fmaf(acc[2], di, bb0.z), fmaf(acc[3], di, bb0.w));
    *(float4*)(ap + 4) = make_float4(fmaf(acc[4], di, bb1.x), fmaf(acc[5], di, bb1.y),
                                     fmaf(acc[6], di, bb1.z), fmaf(acc[7], di, bb1.w));
}

// ---------------- GEMM2: h2h = (relu(agg1) @ W2) * dinv  (fp16 out) ----------------
#define XS2_PITCH 68
__global__ void __launch_bounds__(256) k_gemm2(const float* __restrict__ W2) {
    __shared__ float xs[64 * XS2_PITCH];
    __shared__ float ws[HID * 64];
    const int tid  = threadIdx.x;
    const int row0 = blockIdx.x * 64;

    #pragma unroll
    for (int i = 0; i < 16; i++) {
        int idx = tid + i * 256;
        int k = idx >> 6, c = idx & 63;
        ws[idx] = (c < NCLS) ? W2[k * NCLS + c] : 0.0f;
    }
    #pragma unroll
    for (int i = 0; i < 4; i++) {
        int f = tid + i * 256;
        int r = f >> 4;
        int o = (f & 15) << 2;
        float4 v = make_float4(0.f, 0.f, 0.f, 0.f);
        if (row0 + r < NNODES) {
            float4 a = *(const float4*)(g_agg1 + (size_t)(row0 + r) * HID + o);
            v = make_float4(fmaxf(a.x, 0.f), fmaxf(a.y, 0.f),
                            fmaxf(a.z, 0.f), fmaxf(a.w, 0.f));
        }
        *(float4*)(xs + r * XS2_PITCH + o) = v;
    }
    __syncthreads();

    const int rp = tid >> 3;
    const int cg = tid & 7;
    if (cg >= 5) return;                  // cols 40..63 are padding
    const int r0 = rp * 2;
    const float* xr0 = xs + r0 * XS2_PITCH;
    const float* xr1 = xs + (r0 + 1) * XS2_PITCH;
    const float* wcol = ws + cg * 8;

    u64 acc[2][4];
    #pragma unroll
    for (int r = 0; r < 2; r++)
        #pragma unroll
        for (int j = 0; j < 4; j++) acc[r][j] = 0ull;

    #pragma unroll 4
    for (int k = 0; k < HID; k += 4) {
        float4 xa = *(const float4*)(xr0 + k);
        float4 xb = *(const float4*)(xr1 + k);
        #pragma unroll
        for (int kk = 0; kk < 4; kk++) {
            u64 xa2 = pack2((&xa.x)[kk]);
            u64 xb2 = pack2((&xb.x)[kk]);
            W4 w0, w1;
            w0.v = *(const float4*)(wcol + (k + kk) * 64);
            w1.v = *(const float4*)(wcol + (k + kk) * 64 + 4);
            acc[0][0] = ffma2(w0.u.lo, xa2, acc[0][0]);
            acc[0][1] = ffma2(w0.u.hi, xa2, acc[0][1]);
            acc[0][2] = ffma2(w1.u.lo, xa2, acc[0][2]);
            acc[0][3] = ffma2(w1.u.hi, xa2, acc[0][3]);
            acc[1][0] = ffma2(w0.u.lo, xb2, acc[1][0]);
            acc[1][1] = ffma2(w0.u.hi, xb2, acc[1][1]);
            acc[1][2] = ffma2(w1.u.lo, xb2, acc[1][2]);
            acc[1][3] = ffma2(w1.u.hi, xb2, acc[1][3]);
        }
    }

    #pragma unroll
    for (int r = 0; r < 2; r++) {
        int row = row0 + r0 + r;
        if (row >= NNODES) continue;
        float di = g_dinv[row];
        F2 a0, a1, a2, a3;
        a0.u = acc[r][0]; a1.u = acc[r][1]; a2.u = acc[r][2]; a3.u = acc[r][3];
        uint4 st;
        __half2* sp = (__half2*)&st;
        sp[0] = __floats2half2_rn(a0.f.x * di, a0.f.y * di);
        sp[1] = __floats2half2_rn(a1.f.x * di, a1.f.y * di);
        sp[2] = __floats2half2_rn(a2.f.x * di, a2.f.y * di);
        sp[3] = __floats2half2_rn(a3.f.x * di, a3.f.y * di);
        *(uint4*)(g_h2h + (size_t)row * NCLS + cg * 8) = st;
    }
}

// ---------------- agg2: out[n] = (h2h[n] + sum h2h[src]) * dinv[n] + b2 ----------------
// 5 lanes per node; lane j owns 8 halves (16B).
__global__ void __launch_bounds__(256) k_agg2(const float* __restrict__ b2,
                                              float* __restrict__ out) {
    int t = blockIdx.x * 256 + threadIdx.x;
    int n = t / 5;
    if (n >= NNODES) return;
    int j = t - n * 5;

    int p0, p1;
    node_range(n, p0, p1);

    float acc[8];
    {
        uint4 v = *(const uint4*)(g_h2h + (size_t)n * NCLS + j * 8);
        float2 f0 = h2tof2(v.x), f1 = h2tof2(v.y), f2 = h2tof2(v.z), f3 = h2tof2(v.w);
        acc[0] = f0.x; acc[1] = f0.y; acc[2] = f1.x; acc[3] = f1.y;
        acc[4] = f2.x; acc[5] = f2.y; acc[6] = f3.x; acc[7] = f3.y;
    }
    int p = p0;
    for (; p + 8 <= p1; p += 8) {
        int s[8];
        #pragma unroll
        for (int q = 0; q < 8; q++) s[q] = g_csr_src[p + q];
        uint4 v[8];
        #pragma unroll
        for (int q = 0; q < 8; q++)
            v[q] = *(const uint4*)(g_h2h + (size_t)s[q] * NCLS + j * 8);
        #pragma unroll
        for (int q = 0; q < 8; q++) {
            float2 f0 = h2tof2(v[q].x), f1 = h2tof2(v[q].y);
            float2 f2 = h2tof2(v[q].z), f3 = h2tof2(v[q].w);
            acc[0] += f0.x; acc[1] += f0.y; acc[2] += f1.x; acc[3] += f1.y;
            acc[4] += f2.x; acc[5] += f2.y; acc[6] += f3.x; acc[7] += f3.y;
        }
    }
    for (; p < p1; p++) {
        int s = g_csr_src[p];
        uint4 v = *(const uint4*)(g_h2h + (size_t)s * NCLS + j * 8);
        float2 f0 = h2tof2(v.x), f1 = h2tof2(v.y), f2 = h2tof2(v.z), f3 = h2tof2(v.w);
        acc[0] += f0.x; acc[1] += f0.y; acc[2] += f1.x; acc[3] += f1.y;
        acc[4] += f2.x; acc[5] += f2.y; acc[6] += f3.x; acc[7] += f3.y;
    }
    float di = g_dinv[n];
    float4 bb0 = *(const float4*)(b2 + j * 8);
    float4 bb1 = *(const float4*)(b2 + j * 8 + 4);
    float* op = out + (size_t)n * NCLS + j * 8;
    *(float4*)(op)     = make_float4(fmaf(acc[0], di, bb0.x), fmaf(acc[1], di, bb0.y),
                                     fmaf(acc[2], di, bb0.z), fmaf(acc[3], di, bb0.w));
    *(float4*)(op + 4) = make_float4(fmaf(acc[4], di, bb1.x), fmaf(acc[5], di, bb1.y),
                                     fmaf(acc[6], di, bb1.z), fmaf(acc[7], di, bb1.w));
}

// ---------------- launch ----------------
extern "C" void kernel_launch(void* const* d_in, const int* in_sizes, int n_in,
                              void* d_out, int out_size) {
    const float* x   = (const float*)d_in[0];
    const int*   ei  = (const int*)d_in[1];
    const float* W1  = (const float*)d_in[2];
    const float* b1  = (const float*)d_in[3];
    const float* W2  = (const float*)d_in[4];
    const float* b2  = (const float*)d_in[5];
    float* out = (float*)d_out;

    const int* src = ei;
    const int* dst = ei + NEDGES;

    // lazily-created side stream + events (host objects only; created once)
    static cudaStream_t s_side = nullptr;
    static cudaEvent_t  s_evFork = nullptr, s_evJoin = nullptr;
    if (s_side == nullptr) {
        cudaStreamCreateWithFlags(&s_side, cudaStreamNonBlocking);
        cudaEventCreateWithFlags(&s_evFork, cudaEventDisableTiming);
        cudaEventCreateWithFlags(&s_evJoin, cudaEventDisableTiming);
    }

    // CSR build prefix (produces g_dinv in scan1)
    k_zero<<<(NNODES + 255) / 256, 256>>>();
    k_hist<<<(NEDGES + 255) / 256, 256>>>(dst);
    k_scan1<<<SCAN_BLOCKS, 1024>>>();

    // fork: gemm1 (needs only dinv) overlaps with scan2 + fill
    cudaEventRecord(s_evFork, 0);
    cudaStreamWaitEvent(s_side, s_evFork, 0);
    k_gemm1<<<(NNODES + 127) / 128, 128, 0, s_side>>>(x, W1);
    cudaEventRecord(s_evJoin, s_side);

    k_scan2<<<1, 128>>>();
    k_fill<<<(NEDGES + 255) / 256, 256>>>(src, dst);

    // join: agg1 needs both CSR (fill) and h1h (gemm1)
    cudaStreamWaitEvent(0, s_evJoin, 0);
    k_agg1<<<(NNODES * 8 + 255) / 256, 256>>>(b1);

    // layer 2
    k_gemm2<<<(NNODES + 63) / 64, 256>>>(W2);
    k_agg2<<<(NNODES * 5 + 255) / 256, 256>>>(b2, out);
}

// round 11
// speedup vs baseline: 1.0819x; 1.0819x over previous
#include <cuda_runtime.h>
#include <cuda_fp16.h>
#include <cstdint>

#define NNODES 100000
#define NEDGES 1600000
#define FIN    128
#define HID    64
#define NCLS   40

#define SCAN_BLOCKS 98   // 98 * 1024 >= NNODES

// ---------------- device scratch (allocation-free) ----------------
__device__ int    g_hist[NNODES];
__device__ int    g_cnt[NNODES];
__device__ int    g_offs[NNODES];          // block-local exclusive offsets
__device__ int    g_bsum[SCAN_BLOCKS];
__device__ int    g_boff[SCAN_BLOCKS];     // global block offsets (exclusive)
__device__ int    g_csr_src[NEDGES];
__device__ float  g_dinv[NNODES];
__device__ __half g_h1h[(size_t)NNODES * HID];    // (x @ W1) * dinv[row], fp16
__device__ float  g_agg1[(size_t)NNODES * HID];   // fp32
__device__ __half g_h2h[(size_t)NNODES * NCLS];   // (relu(agg1) @ W2) * dinv[row], fp16

// ---------------- helpers ----------------
typedef unsigned long long u64;
__device__ __forceinline__ u64 ffma2(u64 a, u64 b, u64 c) {
    u64 d;
    asm("fma.rn.f32x2 %0, %1, %2, %3;" : "=l"(d) : "l"(a), "l"(b), "l"(c));
    return d;
}
__device__ __forceinline__ u64 pack2(float x) {
    u64 d;
    asm("mov.b64 %0, {%1, %1};" : "=l"(d) : "f"(x));
    return d;
}
union F2 { u64 u; float2 f; };
union W4 { float4 v; struct { u64 lo, hi; } u; };

__device__ __forceinline__ float2 h2tof2(uint32_t h) {
    __half2 hh = *reinterpret_cast<__half2*>(&h);
    return __half22float2(hh);
}

// global CSR range for node n
__device__ __forceinline__ void node_range(int n, int& p0, int& p1) {
    p0 = g_offs[n] + g_boff[n >> 10];
    int m = n + 1;
    p1 = (m == NNODES) ? NEDGES : (g_offs[m] + g_boff[m >> 10]);
}

// ---------------- CSR build ----------------
__global__ void k_zero() {
    int i = blockIdx.x * blockDim.x + threadIdx.x;
    if (i < NNODES) g_hist[i] = 0;
}
__global__ void k_hist(const int* __restrict__ dst) {
    int e = blockIdx.x * blockDim.x + threadIdx.x;
    if (e < NEDGES) atomicAdd(&g_hist[dst[e]], 1);
}
__global__ void __launch_bounds__(1024) k_scan1() {
    __shared__ int sh[1024];
    int i = blockIdx.x * 1024 + threadIdx.x;
    int h = (i < NNODES) ? g_hist[i] : 0;
    sh[threadIdx.x] = h;
    __syncthreads();
    #pragma unroll
    for (int ofs = 1; ofs < 1024; ofs <<= 1) {
        int v = (threadIdx.x >= ofs) ? sh[threadIdx.x - ofs] : 0;
        __syncthreads();
        sh[threadIdx.x] += v;
        __syncthreads();
    }
    if (i < NNODES) {
        g_offs[i] = sh[threadIdx.x] - h;
        g_dinv[i] = rsqrtf((float)(h + 1));
        g_cnt[i]  = 0;
    }
    if (threadIdx.x == 1023) g_bsum[blockIdx.x] = sh[1023];
}
__global__ void __launch_bounds__(128) k_scan2() {
    __shared__ int sh[128];
    int t = threadIdx.x;
    int v = (t < SCAN_BLOCKS) ? g_bsum[t] : 0;
    sh[t] = v;
    __syncthreads();
    #pragma unroll
    for (int ofs = 1; ofs < 128; ofs <<= 1) {
        int u = (t >= ofs) ? sh[t - ofs] : 0;
        __syncthreads();
        sh[t] += u;
        __syncthreads();
    }
    if (t < SCAN_BLOCKS) g_boff[t] = sh[t] - v;
}
__global__ void k_fill(const int* __restrict__ src, const int* __restrict__ dst) {
    int e = blockIdx.x * blockDim.x + threadIdx.x;
    if (e >= NEDGES) return;
    int s = src[e], d = dst[e];
    int pos = g_offs[d] + g_boff[d >> 10] + atomicAdd(&g_cnt[d], 1);
    g_csr_src[pos] = s;
}

// ---------------- GEMM1: h1h = (x @ W1) * dinv  (fp16 out) ----------------
// 256 threads, 128-row tile; thread = 8 rows x 4 cols (16 u64 accumulators).
#define XS_PITCH 132
__global__ void __launch_bounds__(256, 2) k_gemm1(const float* __restrict__ x,
                                                  const float* __restrict__ W1) {
    __shared__ float xs[128 * XS_PITCH];  // 67.6 KB
    __shared__ float ws[FIN * HID];       // 32 KB
    const int tid  = threadIdx.x;
    const int row0 = blockIdx.x * 128;

    {   // load W1 (2048 float4)
        const float4* wsrc = (const float4*)W1;
        float4* wdst = (float4*)ws;
        #pragma unroll
        for (int i = 0; i < 8; i++) wdst[tid + i * 256] = wsrc[tid + i * 256];
    }
    {   // load x tile (4096 float4)
        #pragma unroll
        for (int i = 0; i < 16; i++) {
            int f = tid + i * 256;
            int r = f >> 5;
            int o = (f & 31) << 2;
            float4 v = make_float4(0.f, 0.f, 0.f, 0.f);
            if (row0 + r < NNODES) v = *(const float4*)(x + (size_t)(row0 + r) * FIN + o);
            *(float4*)(xs + r * XS_PITCH + o) = v;
        }
    }
    __syncthreads();

    const int rp = tid >> 4;              // 0..15 -> rows rp*8..rp*8+7
    const int cg = tid & 15;              // 0..15 -> cols cg*4..cg*4+3
    const float* wcol = ws + cg * 4;
    const float* xr = xs + (rp * 8) * XS_PITCH;

    u64 acc[8][2];
    #pragma unroll
    for (int r = 0; r < 8; r++) { acc[r][0] = 0ull; acc[r][1] = 0ull; }

    #pragma unroll 2
    for (int k = 0; k < FIN; k += 4) {
        float4 xa[8];
        #pragma unroll
        for (int r = 0; r < 8; r++)
            xa[r] = *(const float4*)(xr + r * XS_PITCH + k);
        #pragma unroll
        for (int kk = 0; kk < 4; kk++) {
            W4 w;
            w.v = *(const float4*)(wcol + (k + kk) * HID);
            #pragma unroll
            for (int r = 0; r < 8; r++) {
                u64 xv = pack2((&xa[r].x)[kk]);
                acc[r][0] = ffma2(w.u.lo, xv, acc[r][0]);
                acc[r][1] = ffma2(w.u.hi, xv, acc[r][1]);
            }
        }
    }

    #pragma unroll
    for (int r = 0; r < 8; r++) {
        int row = row0 + rp * 8 + r;
        if (row >= NNODES) continue;
        float di = g_dinv[row];
        F2 a0, a1;
        a0.u = acc[r][0]; a1.u = acc[r][1];
        uint2 st;
        __half2* sp = (__half2*)&st;
        sp[0] = __floats2half2_rn(a0.f.x * di, a0.f.y * di);
        sp[1] = __floats2half2_rn(a1.f.x * di, a1.f.y * di);
        *(uint2*)(g_h1h + (size_t)row * HID + cg * 4) = st;
    }
}

// ---------------- agg1: agg1[n] = (h1h[n] + sum h1h[src]) * dinv[n] + b1 ----------------
// 8 lanes per node; lane j owns 8 halves (16B).
__global__ void __launch_bounds__(256) k_agg1(const float* __restrict__ b1) {
    int t = blockIdx.x * 256 + threadIdx.x;
    int n = t >> 3;
    if (n >= NNODES) return;
    int j = t & 7;

    int p0, p1;
    node_range(n, p0, p1);

    float acc[8];
    {   // self-loop seed
        uint4 v = *(const uint4*)(g_h1h + (size_t)n * HID + j * 8);
        float2 f0 = h2tof2(v.x), f1 = h2tof2(v.y), f2 = h2tof2(v.z), f3 = h2tof2(v.w);
        acc[0] = f0.x; acc[1] = f0.y; acc[2] = f1.x; acc[3] = f1.y;
        acc[4] = f2.x; acc[5] = f2.y; acc[6] = f3.x; acc[7] = f3.y;
    }
    int p = p0;
    for (; p + 8 <= p1; p += 8) {
        int s[8];
        #pragma unroll
        for (int q = 0; q < 8; q++) s[q] = g_csr_src[p + q];
        uint4 v[8];
        #pragma unroll
        for (int q = 0; q < 8; q++)
            v[q] = *(const uint4*)(g_h1h + (size_t)s[q] * HID + j * 8);
        #pragma unroll
        for (int q = 0; q < 8; q++) {
            float2 f0 = h2tof2(v[q].x), f1 = h2tof2(v[q].y);
            float2 f2 = h2tof2(v[q].z), f3 = h2tof2(v[q].w);
            acc[0] += f0.x; acc[1] += f0.y; acc[2] += f1.x; acc[3] += f1.y;
            acc[4] += f2.x; acc[5] += f2.y; acc[6] += f3.x; acc[7] += f3.y;
        }
    }
    for (; p < p1; p++) {
        int s = g_csr_src[p];
        uint4 v = *(const uint4*)(g_h1h + (size_t)s * HID + j * 8);
        float2 f0 = h2tof2(v.x), f1 = h2tof2(v.y), f2 = h2tof2(v.z), f3 = h2tof2(v.w);
        acc[0] += f0.x; acc[1] += f0.y; acc[2] += f1.x; acc[3] += f1.y;
        acc[4] += f2.x; acc[5] += f2.y; acc[6] += f3.x; acc[7] += f3.y;
    }
    float di = g_dinv[n];
    float4 bb0 = *(const float4*)(b1 + j * 8);
    float4 bb1 = *(const float4*)(b1 + j * 8 + 4);
    float* ap = g_agg1 + (size_t)n * HID + j * 8;
    *(float4*)(ap)     = make_float4(fmaf(acc[0], di, bb0.x), fmaf(acc[1], di, bb0.y),
                                     fmaf(acc[2], di, bb0.z), fmaf(acc[3], di, bb0.w));
    *(float4*)(ap + 4) = make_float4(fmaf(acc[4], di, bb1.x), fmaf(acc[5], di, bb1.y),
                                     fmaf(acc[6], di, bb1.z), fmaf(acc[7], di, bb1.w));
}

// ---------------- GEMM2: h2h = (relu(agg1) @ W2) * dinv  (fp16 out) ----------------
#define XS2_PITCH 68
__global__ void __launch_bounds__(256) k_gemm2(const float* __restrict__ W2) {
    __shared__ float xs[64 * XS2_PITCH];
    __shared__ float ws[HID * 64];
    const int tid  = threadIdx.x;
    const int row0 = blockIdx.x * 64;

    #pragma unroll
    for (int i = 0; i < 16; i++) {
        int idx = tid + i * 256;
        int k = idx >> 6, c = idx & 63;
        ws[idx] = (c < NCLS) ? W2[k * NCLS + c] : 0.0f;
    }
    #pragma unroll
    for (int i = 0; i < 4; i++) {
        int f = tid + i * 256;
        int r = f >> 4;
        int o = (f & 15) << 2;
        float4 v = make_float4(0.f, 0.f, 0.f, 0.f);
        if (row0 + r < NNODES) {
            float4 a = *(const float4*)(g_agg1 + (size_t)(row0 + r) * HID + o);
            v = make_float4(fmaxf(a.x, 0.f), fmaxf(a.y, 0.f),
                            fmaxf(a.z, 0.f), fmaxf(a.w, 0.f));
        }
        *(float4*)(xs + r * XS2_PITCH + o) = v;
    }
    __syncthreads();

    const int rp = tid >> 3;
    const int cg = tid & 7;
    if (cg >= 5) return;                  // cols 40..63 are padding
    const int r0 = rp * 2;
    const float* xr0 = xs + r0 * XS2_PITCH;
    const float* xr1 = xs + (r0 + 1) * XS2_PITCH;
    const float* wcol = ws + cg * 8;

    u64 acc[2][4];
    #pragma unroll
    for (int r = 0; r < 2; r++)
        #pragma unroll
        for (int j = 0; j < 4; j++) acc[r][j] = 0ull;

    #pragma unroll 4
    for (int k = 0; k < HID; k += 4) {
        float4 xa = *(const float4*)(xr0 + k);
        float4 xb = *(const float4*)(xr1 + k);
        #pragma unroll
        for (int kk = 0; kk < 4; kk++) {
            u64 xa2 = pack2((&xa.x)[kk]);
            u64 xb2 = pack2((&xb.x)[kk]);
            W4 w0, w1;
            w0.v = *(const float4*)(wcol + (k + kk) * 64);
            w1.v = *(const float4*)(wcol + (k + kk) * 64 + 4);
            acc[0][0] = ffma2(w0.u.lo, xa2, acc[0][0]);
            acc[0][1] = ffma2(w0.u.hi, xa2, acc[0][1]);
            acc[0][2] = ffma2(w1.u.lo, xa2, acc[0][2]);
            acc[0][3] = ffma2(w1.u.hi, xa2, acc[0][3]);
            acc[1][0] = ffma2(w0.u.lo, xb2, acc[1][0]);
            acc[1][1] = ffma2(w0.u.hi, xb2, acc[1][1]);
            acc[1][2] = ffma2(w1.u.lo, xb2, acc[1][2]);
            acc[1][3] = ffma2(w1.u.hi, xb2, acc[1][3]);
        }
    }

    #pragma unroll
    for (int r = 0; r < 2; r++) {
        int row = row0 + r0 + r;
        if (row >= NNODES) continue;
        float di = g_dinv[row];
        F2 a0, a1, a2, a3;
        a0.u = acc[r][0]; a1.u = acc[r][1]; a2.u = acc[r][2]; a3.u = acc[r][3];
        uint4 st;
        __half2* sp = (__half2*)&st;
        sp[0] = __floats2half2_rn(a0.f.x * di, a0.f.y * di);
        sp[1] = __floats2half2_rn(a1.f.x * di, a1.f.y * di);
        sp[2] = __floats2half2_rn(a2.f.x * di, a2.f.y * di);
        sp[3] = __floats2half2_rn(a3.f.x * di, a3.f.y * di);
        *(uint4*)(g_h2h + (size_t)row * NCLS + cg * 8) = st;
    }
}

// ---------------- agg2: out[n] = (h2h[n] + sum h2h[src]) * dinv[n] + b2 ----------------
// 5 lanes per node; lane j owns 8 halves (16B).
__global__ void __launch_bounds__(256) k_agg2(const float* __restrict__ b2,
                                              float* __restrict__ out) {
    int t = blockIdx.x * 256 + threadIdx.x;
    int n = t / 5;
    if (n >= NNODES) return;
    int j = t - n * 5;

    int p0, p1;
    node_range(n, p0, p1);

    float acc[8];
    {
        uint4 v = *(const uint4*)(g_h2h + (size_t)n * NCLS + j * 8);
        float2 f0 = h2tof2(v.x), f1 = h2tof2(v.y), f2 = h2tof2(v.z), f3 = h2tof2(v.w);
        acc[0] = f0.x; acc[1] = f0.y; acc[2] = f1.x; acc[3] = f1.y;
        acc[4] = f2.x; acc[5] = f2.y; acc[6] = f3.x; acc[7] = f3.y;
    }
    int p = p0;
    for (; p + 8 <= p1; p += 8) {
        int s[8];
        #pragma unroll
        for (int q = 0; q < 8; q++) s[q] = g_csr_src[p + q];
        uint4 v[8];
        #pragma unroll
        for (int q = 0; q < 8; q++)
            v[q] = *(const uint4*)(g_h2h + (size_t)s[q] * NCLS + j * 8);
        #pragma unroll
        for (int q = 0; q < 8; q++) {
            float2 f0 = h2tof2(v[q].x), f1 = h2tof2(v[q].y);
            float2 f2 = h2tof2(v[q].z), f3 = h2tof2(v[q].w);
            acc[0] += f0.x; acc[1] += f0.y; acc[2] += f1.x; acc[3] += f1.y;
            acc[4] += f2.x; acc[5] += f2.y; acc[6] += f3.x; acc[7] += f3.y;
        }
    }
    for (; p < p1; p++) {
        int s = g_csr_src[p];
        uint4 v = *(const uint4*)(g_h2h + (size_t)s * NCLS + j * 8);
        float2 f0 = h2tof2(v.x), f1 = h2tof2(v.y), f2 = h2tof2(v.z), f3 = h2tof2(v.w);
        acc[0] += f0.x; acc[1] += f0.y; acc[2] += f1.x; acc[3] += f1.y;
        acc[4] += f2.x; acc[5] += f2.y; acc[6] += f3.x; acc[7] += f3.y;
    }
    float di = g_dinv[n];
    float4 bb0 = *(const float4*)(b2 + j * 8);
    float4 bb1 = *(const float4*)(b2 + j * 8 + 4);
    float* op = out + (size_t)n * NCLS + j * 8;
    *(float4*)(op)     = make_float4(fmaf(acc[0], di, bb0.x), fmaf(acc[1], di, bb0.y),
                                     fmaf(acc[2], di, bb0.z), fmaf(acc[3], di, bb0.w));
    *(float4*)(op + 4) = make_float4(fmaf(acc[4], di, bb1.x), fmaf(acc[5], di, bb1.y),
                                     fmaf(acc[6], di, bb1.z), fmaf(acc[7], di, bb1.w));
}

// ---------------- launch ----------------
extern "C" void kernel_launch(void* const* d_in, const int* in_sizes, int n_in,
                              void* d_out, int out_size) {
    const float* x   = (const float*)d_in[0];
    const int*   ei  = (const int*)d_in[1];
    const float* W1  = (const float*)d_in[2];
    const float* b1  = (const float*)d_in[3];
    const float* W2  = (const float*)d_in[4];
    const float* b2  = (const float*)d_in[5];
    float* out = (float*)d_out;

    const int* src = ei;
    const int* dst = ei + NEDGES;

    // CSR build + dinv (serial stream — fork experiment regressed, reverted)
    k_zero<<<(NNODES + 255) / 256, 256>>>();
    k_hist<<<(NEDGES + 255) / 256, 256>>>(dst);
    k_scan1<<<SCAN_BLOCKS, 1024>>>();
    k_scan2<<<1, 128>>>();
    k_fill<<<(NEDGES + 255) / 256, 256>>>(src, dst);

    // layer 1
    k_gemm1<<<(NNODES + 127) / 128, 256>>>(x, W1);
    k_agg1<<<(NNODES * 8 + 255) / 256, 256>>>(b1);

    // layer 2
    k_gemm2<<<(NNODES + 63) / 64, 256>>>(W2);
    k_agg2<<<(NNODES * 5 + 255) / 256, 256>>>(b2, out);
}

// round 12
// speedup vs baseline: 1.3079x; 1.2089x over previous
#include <cuda_runtime.h>
#include <cuda_fp16.h>
#include <cstdint>

#define NNODES 100000
#define NEDGES 1600000
#define FIN    128
#define HID    64
#define NCLS   40

#define SCAN_BLOCKS 98   // 98 * 1024 >= NNODES

// ---------------- device scratch (allocation-free) ----------------
__device__ int    g_hist[NNODES];
__device__ int    g_cnt[NNODES];
__device__ int    g_offs[NNODES];          // block-local exclusive offsets
__device__ int    g_bsum[SCAN_BLOCKS];
__device__ int    g_boff[SCAN_BLOCKS];     // global block offsets (exclusive)
__device__ int    g_csr_src[NEDGES];
__device__ float  g_dinv[NNODES];
__device__ __half g_h1h[(size_t)NNODES * HID];    // (x @ W1) * dinv[row], fp16
__device__ __half g_agg1h[(size_t)NNODES * HID];  // relu(layer-1 agg), fp16
__device__ __half g_h2h[(size_t)NNODES * NCLS];   // (relu_agg1 @ W2) * dinv[row], fp16

// ---------------- helpers ----------------
typedef unsigned long long u64;
__device__ __forceinline__ u64 ffma2(u64 a, u64 b, u64 c) {
    u64 d;
    asm("fma.rn.f32x2 %0, %1, %2, %3;" : "=l"(d) : "l"(a), "l"(b), "l"(c));
    return d;
}
__device__ __forceinline__ u64 pack2(float x) {
    u64 d;
    asm("mov.b64 %0, {%1, %1};" : "=l"(d) : "f"(x));
    return d;
}
union F2 { u64 u; float2 f; };
union W4 { float4 v; struct { u64 lo, hi; } u; };

__device__ __forceinline__ float2 h2tof2(uint32_t h) {
    __half2 hh = *reinterpret_cast<__half2*>(&h);
    return __half22float2(hh);
}

// global CSR range for node n
__device__ __forceinline__ void node_range(int n, int& p0, int& p1) {
    p0 = g_offs[n] + g_boff[n >> 10];
    int m = n + 1;
    p1 = (m == NNODES) ? NEDGES : (g_offs[m] + g_boff[m >> 10]);
}

// ---------------- CSR build ----------------
__global__ void k_zero() {
    int i = blockIdx.x * blockDim.x + threadIdx.x;
    if (i < NNODES) g_hist[i] = 0;
}
__global__ void k_hist(const int* __restrict__ dst) {
    int e = blockIdx.x * blockDim.x + threadIdx.x;
    if (e < NEDGES) atomicAdd(&g_hist[dst[e]], 1);
}
__global__ void __launch_bounds__(1024) k_scan1() {
    __shared__ int sh[1024];
    int i = blockIdx.x * 1024 + threadIdx.x;
    int h = (i < NNODES) ? g_hist[i] : 0;
    sh[threadIdx.x] = h;
    __syncthreads();
    #pragma unroll
    for (int ofs = 1; ofs < 1024; ofs <<= 1) {
        int v = (threadIdx.x >= ofs) ? sh[threadIdx.x - ofs] : 0;
        __syncthreads();
        sh[threadIdx.x] += v;
        __syncthreads();
    }
    if (i < NNODES) {
        g_offs[i] = sh[threadIdx.x] - h;
        g_dinv[i] = rsqrtf((float)(h + 1));
        g_cnt[i]  = 0;
    }
    if (threadIdx.x == 1023) g_bsum[blockIdx.x] = sh[1023];
}
__global__ void __launch_bounds__(128) k_scan2() {
    __shared__ int sh[128];
    int t = threadIdx.x;
    int v = (t < SCAN_BLOCKS) ? g_bsum[t] : 0;
    sh[t] = v;
    __syncthreads();
    #pragma unroll
    for (int ofs = 1; ofs < 128; ofs <<= 1) {
        int u = (t >= ofs) ? sh[t - ofs] : 0;
        __syncthreads();
        sh[t] += u;
        __syncthreads();
    }
    if (t < SCAN_BLOCKS) g_boff[t] = sh[t] - v;
}
__global__ void k_fill(const int* __restrict__ src, const int* __restrict__ dst) {
    int e = blockIdx.x * blockDim.x + threadIdx.x;
    if (e >= NEDGES) return;
    int s = src[e], d = dst[e];
    int pos = g_offs[d] + g_boff[d >> 10] + atomicAdd(&g_cnt[d], 1);
    g_csr_src[pos] = s;
}

// ---------------- GEMM1: h1h = (x @ W1) * dinv  (fp16 out) ----------------
// 256 threads, 128-row tile; thread = 8 rows x 4 cols (16 u64 accumulators).
#define XS_PITCH 132
__global__ void __launch_bounds__(256, 2) k_gemm1(const float* __restrict__ x,
                                                  const float* __restrict__ W1) {
    __shared__ float xs[128 * XS_PITCH];  // 67.6 KB
    __shared__ float ws[FIN * HID];       // 32 KB
    const int tid  = threadIdx.x;
    const int row0 = blockIdx.x * 128;

    {   // load W1 (2048 float4)
        const float4* wsrc = (const float4*)W1;
        float4* wdst = (float4*)ws;
        #pragma unroll
        for (int i = 0; i < 8; i++) wdst[tid + i * 256] = wsrc[tid + i * 256];
    }
    {   // load x tile (4096 float4)
        #pragma unroll
        for (int i = 0; i < 16; i++) {
            int f = tid + i * 256;
            int r = f >> 5;
            int o = (f & 31) << 2;
            float4 v = make_float4(0.f, 0.f, 0.f, 0.f);
            if (row0 + r < NNODES) v = *(const float4*)(x + (size_t)(row0 + r) * FIN + o);
            *(float4*)(xs + r * XS_PITCH + o) = v;
        }
    }
    __syncthreads();

    const int rp = tid >> 4;              // 0..15 -> rows rp*8..rp*8+7
    const int cg = tid & 15;              // 0..15 -> cols cg*4..cg*4+3
    const float* wcol = ws + cg * 4;
    const float* xr = xs + (rp * 8) * XS_PITCH;

    u64 acc[8][2];
    #pragma unroll
    for (int r = 0; r < 8; r++) { acc[r][0] = 0ull; acc[r][1] = 0ull; }

    #pragma unroll 2
    for (int k = 0; k < FIN; k += 4) {
        float4 xa[8];
        #pragma unroll
        for (int r = 0; r < 8; r++)
            xa[r] = *(const float4*)(xr + r * XS_PITCH + k);
        #pragma unroll
        for (int kk = 0; kk < 4; kk++) {
            W4 w;
            w.v = *(const float4*)(wcol + (k + kk) * HID);
            #pragma unroll
            for (int r = 0; r < 8; r++) {
                u64 xv = pack2((&xa[r].x)[kk]);
                acc[r][0] = ffma2(w.u.lo, xv, acc[r][0]);
                acc[r][1] = ffma2(w.u.hi, xv, acc[r][1]);
            }
        }
    }

    #pragma unroll
    for (int r = 0; r < 8; r++) {
        int row = row0 + rp * 8 + r;
        if (row >= NNODES) continue;
        float di = g_dinv[row];
        F2 a0, a1;
        a0.u = acc[r][0]; a1.u = acc[r][1];
        uint2 st;
        __half2* sp = (__half2*)&st;
        sp[0] = __floats2half2_rn(a0.f.x * di, a0.f.y * di);
        sp[1] = __floats2half2_rn(a1.f.x * di, a1.f.y * di);
        *(uint2*)(g_h1h + (size_t)row * HID + cg * 4) = st;
    }
}

// ---------------- agg1: agg1h[n] = relu((h1h[n] + sum h1h[src]) * dinv[n] + b1), fp16 ----------------
// 8 lanes per node; lane j owns 8 halves (16B).
__global__ void __launch_bounds__(256) k_agg1(const float* __restrict__ b1) {
    int t = blockIdx.x * 256 + threadIdx.x;
    int n = t >> 3;
    if (n >= NNODES) return;
    int j = t & 7;

    int p0, p1;
    node_range(n, p0, p1);

    float acc[8];
    {   // self-loop seed
        uint4 v = *(const uint4*)(g_h1h + (size_t)n * HID + j * 8);
        float2 f0 = h2tof2(v.x), f1 = h2tof2(v.y), f2 = h2tof2(v.z), f3 = h2tof2(v.w);
        acc[0] = f0.x; acc[1] = f0.y; acc[2] = f1.x; acc[3] = f1.y;
        acc[4] = f2.x; acc[5] = f2.y; acc[6] = f3.x; acc[7] = f3.y;
    }
    int p = p0;
    for (; p + 8 <= p1; p += 8) {
        int s[8];
        #pragma unroll
        for (int q = 0; q < 8; q++) s[q] = g_csr_src[p + q];
        uint4 v[8];
        #pragma unroll
        for (int q = 0; q < 8; q++)
            v[q] = *(const uint4*)(g_h1h + (size_t)s[q] * HID + j * 8);
        #pragma unroll
        for (int q = 0; q < 8; q++) {
            float2 f0 = h2tof2(v[q].x), f1 = h2tof2(v[q].y);
            float2 f2 = h2tof2(v[q].z), f3 = h2tof2(v[q].w);
            acc[0] += f0.x; acc[1] += f0.y; acc[2] += f1.x; acc[3] += f1.y;
            acc[4] += f2.x; acc[5] += f2.y; acc[6] += f3.x; acc[7] += f3.y;
        }
    }
    for (; p < p1; p++) {
        int s = g_csr_src[p];
        uint4 v = *(const uint4*)(g_h1h + (size_t)s * HID + j * 8);
        float2 f0 = h2tof2(v.x), f1 = h2tof2(v.y), f2 = h2tof2(v.z), f3 = h2tof2(v.w);
        acc[0] += f0.x; acc[1] += f0.y; acc[2] += f1.x; acc[3] += f1.y;
        acc[4] += f2.x; acc[5] += f2.y; acc[6] += f3.x; acc[7] += f3.y;
    }
    float di = g_dinv[n];
    float4 bb0 = *(const float4*)(b1 + j * 8);
    float4 bb1 = *(const float4*)(b1 + j * 8 + 4);
    float o0 = fmaxf(fmaf(acc[0], di, bb0.x), 0.f);
    float o1 = fmaxf(fmaf(acc[1], di, bb0.y), 0.f);
    float o2 = fmaxf(fmaf(acc[2], di, bb0.z), 0.f);
    float o3 = fmaxf(fmaf(acc[3], di, bb0.w), 0.f);
    float o4 = fmaxf(fmaf(acc[4], di, bb1.x), 0.f);
    float o5 = fmaxf(fmaf(acc[5], di, bb1.y), 0.f);
    float o6 = fmaxf(fmaf(acc[6], di, bb1.z), 0.f);
    float o7 = fmaxf(fmaf(acc[7], di, bb1.w), 0.f);
    uint4 st;
    __half2* sp = (__half2*)&st;
    sp[0] = __floats2half2_rn(o0, o1);
    sp[1] = __floats2half2_rn(o2, o3);
    sp[2] = __floats2half2_rn(o4, o5);
    sp[3] = __floats2half2_rn(o6, o7);
    *(uint4*)(g_agg1h + (size_t)n * HID + j * 8) = st;
}

// ---------------- GEMM2: h2h = (agg1h @ W2) * dinv  (fp16 in/out) ----------------
// 256 threads, 128-row tile; thread = 8 rows x 4 cols; col groups 10..15 idle.
#define XS2_PITCH 68
__global__ void __launch_bounds__(256, 2) k_gemm2(const float* __restrict__ W2) {
    __shared__ float xs[128 * XS2_PITCH];  // 34.8 KB
    __shared__ float ws[HID * 64];         // 16 KB (cols padded 40->64)
    const int tid  = threadIdx.x;
    const int row0 = blockIdx.x * 128;

    // W2 [64][40] -> ws [64][64] zero-padded
    #pragma unroll
    for (int i = 0; i < 16; i++) {
        int idx = tid + i * 256;
        int k = idx >> 6, c = idx & 63;
        ws[idx] = (c < NCLS) ? W2[k * NCLS + c] : 0.0f;
    }
    // agg1h tile: 128 rows x 64 halves = 1024 chunks of 8 halves (uint4)
    #pragma unroll
    for (int i = 0; i < 4; i++) {
        int f = tid + i * 256;            // [0, 1024)
        int r = f >> 3;
        int c = f & 7;                    // 8-half chunk
        float v[8] = {0.f, 0.f, 0.f, 0.f, 0.f, 0.f, 0.f, 0.f};
        if (row0 + r < NNODES) {
            uint4 h = *(const uint4*)(g_agg1h + (size_t)(row0 + r) * HID + c * 8);
            float2 f0 = h2tof2(h.x), f1 = h2tof2(h.y), f2 = h2tof2(h.z), f3 = h2tof2(h.w);
            v[0] = f0.x; v[1] = f0.y; v[2] = f1.x; v[3] = f1.y;
            v[4] = f2.x; v[5] = f2.y; v[6] = f3.x; v[7] = f3.y;
        }
        float* xp = xs + r * XS2_PITCH + c * 8;
        *(float4*)(xp)     = make_float4(v[0], v[1], v[2], v[3]);
        *(float4*)(xp + 4) = make_float4(v[4], v[5], v[6], v[7]);
    }
    __syncthreads();

    const int rp = tid >> 4;              // 0..15 -> rows rp*8..rp*8+7
    const int cg = tid & 15;              // 0..15; only cg<10 produce output
    if (cg >= 10) return;
    const float* wcol = ws + cg * 4;
    const float* xr = xs + (rp * 8) * XS2_PITCH;

    u64 acc[8][2];
    #pragma unroll
    for (int r = 0; r < 8; r++) { acc[r][0] = 0ull; acc[r][1] = 0ull; }

    #pragma unroll 2
    for (int k = 0; k < HID; k += 4) {
        float4 xa[8];
        #pragma unroll
        for (int r = 0; r < 8; r++)
            xa[r] = *(const float4*)(xr + r * XS2_PITCH + k);
        #pragma unroll
        for (int kk = 0; kk < 4; kk++) {
            W4 w;
            w.v = *(const float4*)(wcol + (k + kk) * 64);
            #pragma unroll
            for (int r = 0; r < 8; r++) {
                u64 xv = pack2((&xa[r].x)[kk]);
                acc[r][0] = ffma2(w.u.lo, xv, acc[r][0]);
                acc[r][1] = ffma2(w.u.hi, xv, acc[r][1]);
            }
        }
    }

    #pragma unroll
    for (int r = 0; r < 8; r++) {
        int row = row0 + rp * 8 + r;
        if (row >= NNODES) continue;
        float di = g_dinv[row];
        F2 a0, a1;
        a0.u = acc[r][0]; a1.u = acc[r][1];
        uint2 st;
        __half2* sp = (__half2*)&st;
        sp[0] = __floats2half2_rn(a0.f.x * di, a0.f.y * di);
        sp[1] = __floats2half2_rn(a1.f.x * di, a1.f.y * di);
        *(uint2*)(g_h2h + (size_t)row * NCLS + cg * 4) = st;
    }
}

// ---------------- agg2: out[n] = (h2h[n] + sum h2h[src]) * dinv[n] + b2 ----------------
// 5 lanes per node; lane j owns 8 halves (16B).
__global__ void __launch_bounds__(256) k_agg2(const float* __restrict__ b2,
                                              float* __restrict__ out) {
    int t = blockIdx.x * 256 + threadIdx.x;
    int n = t / 5;
    if (n >= NNODES) return;
    int j = t - n * 5;

    int p0, p1;
    node_range(n, p0, p1);

    float acc[8];
    {
        uint4 v = *(const uint4*)(g_h2h + (size_t)n * NCLS + j * 8);
        float2 f0 = h2tof2(v.x), f1 = h2tof2(v.y), f2 = h2tof2(v.z), f3 = h2tof2(v.w);
        acc[0] = f0.x; acc[1] = f0.y; acc[2] = f1.x; acc[3] = f1.y;
        acc[4] = f2.x; acc[5] = f2.y; acc[6] = f3.x; acc[7] = f3.y;
    }
    int p = p0;
    for (; p + 8 <= p1; p += 8) {
        int s[8];
        #pragma unroll
        for (int q = 0; q < 8; q++) s[q] = g_csr_src[p + q];
        uint4 v[8];
        #pragma unroll
        for (int q = 0; q < 8; q++)
            v[q] = *(const uint4*)(g_h2h + (size_t)s[q] * NCLS + j * 8);
        #pragma unroll
        for (int q = 0; q < 8; q++) {
            float2 f0 = h2tof2(v[q].x), f1 = h2tof2(v[q].y);
            float2 f2 = h2tof2(v[q].z), f3 = h2tof2(v[q].w);
            acc[0] += f0.x; acc[1] += f0.y; acc[2] += f1.x; acc[3] += f1.y;
            acc[4] += f2.x; acc[5] += f2.y; acc[6] += f3.x; acc[7] += f3.y;
        }
    }
    for (; p < p1; p++) {
        int s = g_csr_src[p];
        uint4 v = *(const uint4*)(g_h2h + (size_t)s * NCLS + j * 8);
        float2 f0 = h2tof2(v.x), f1 = h2tof2(v.y), f2 = h2tof2(v.z), f3 = h2tof2(v.w);
        acc[0] += f0.x; acc[1] += f0.y; acc[2] += f1.x; acc[3] += f1.y;
        acc[4] += f2.x; acc[5] += f2.y; acc[6] += f3.x; acc[7] += f3.y;
    }
    float di = g_dinv[n];
    float4 bb0 = *(const float4*)(b2 + j * 8);
    float4 bb1 = *(const float4*)(b2 + j * 8 + 4);
    float* op = out + (size_t)n * NCLS + j * 8;
    *(float4*)(op)     = make_float4(fmaf(acc[0], di, bb0.x), fmaf(acc[1], di, bb0.y),
                                     fmaf(acc[2], di, bb0.z), fmaf(acc[3], di, bb0.w));
    *(float4*)(op + 4) = make_float4(fmaf(acc[4], di, bb1.x), fmaf(acc[5], di, bb1.y),
                                     fmaf(acc[6], di, bb1.z), fmaf(acc[7], di, bb1.w));
}

// ---------------- launch ----------------
extern "C" void kernel_launch(void* const* d_in, const int* in_sizes, int n_in,
                              void* d_out, int out_size) {
    const float* x   = (const float*)d_in[0];
    const int*   ei  = (const int*)d_in[1];
    const float* W1  = (const float*)d_in[2];
    const float* b1  = (const float*)d_in[3];
    const float* W2  = (const float*)d_in[4];
    const float* b2  = (const float*)d_in[5];
    float* out = (float*)d_out;

    const int* src = ei;
    const int* dst = ei + NEDGES;

    // CSR build + dinv
    k_zero<<<(NNODES + 255) / 256, 256>>>();
    k_hist<<<(NEDGES + 255) / 256, 256>>>(dst);
    k_scan1<<<SCAN_BLOCKS, 1024>>>();
    k_scan2<<<1, 128>>>();
    k_fill<<<(NEDGES + 255) / 256, 256>>>(src, dst);

    // layer 1
    k_gemm1<<<(NNODES + 127) / 128, 256>>>(x, W1);
    k_agg1<<<(NNODES * 8 + 255) / 256, 256>>>(b1);

    // layer 2
    k_gemm2<<<(NNODES + 127) / 128, 256>>>(W2);
    k_agg2<<<(NNODES * 5 + 255) / 256, 256>>>(b2, out);
}

// round 13
// speedup vs baseline: 1.3255x; 1.0134x over previous
#include <cuda_runtime.h>
#include <cuda_fp16.h>
#include <cstdint>

#define NNODES 100000
#define NEDGES 1600000
#define FIN    128
#define HID    64
#define NCLS   40

#define SCAN_BLOCKS 98   // 98 * 1024 >= NNODES

// ---------------- device scratch (allocation-free) ----------------
__device__ int    g_hist[NNODES];
__device__ int    g_cnt[NNODES];
__device__ int    g_offs[NNODES];          // block-local exclusive offsets
__device__ int    g_boff[SCAN_BLOCKS];     // per-block base in edge array (atomic chunk)
__device__ int    g_total;                 // chunk-reservation counter
__device__ int    g_csr_src[NEDGES];
__device__ float  g_dinv[NNODES];
__device__ __half g_h1h[(size_t)NNODES * HID];    // (x @ W1) * dinv[row], fp16
__device__ __half g_agg1h[(size_t)NNODES * HID];  // relu(layer-1 agg), fp16
__device__ __half g_h2h[(size_t)NNODES * NCLS];   // (relu_agg1 @ W2) * dinv[row], fp16

// ---------------- helpers ----------------
typedef unsigned long long u64;
__device__ __forceinline__ u64 ffma2(u64 a, u64 b, u64 c) {
    u64 d;
    asm("fma.rn.f32x2 %0, %1, %2, %3;" : "=l"(d) : "l"(a), "l"(b), "l"(c));
    return d;
}
__device__ __forceinline__ u64 pack2(float x) {
    u64 d;
    asm("mov.b64 %0, {%1, %1};" : "=l"(d) : "f"(x));
    return d;
}
union F2 { u64 u; float2 f; };
union W4 { float4 v; struct { u64 lo, hi; } u; };

__device__ __forceinline__ float2 h2tof2(uint32_t h) {
    __half2 hh = *reinterpret_cast<__half2*>(&h);
    return __half22float2(hh);
}

// global CSR range for node n
__device__ __forceinline__ void node_range(int n, int& p0, int& p1) {
    p0 = g_offs[n] + g_boff[n >> 10];
    int m = n + 1;
    // last node of a block: range ends at block base + block total = offs within next... 
    // handled by storing per-node count implicitly: p1 computed from same block only if m in same block.
    if ((m >> 10) == (n >> 10) && m < NNODES)
        p1 = g_offs[m] + g_boff[m >> 10];
    else
        p1 = g_offs[n] + g_boff[n >> 10] + g_hist[n];   // last node in block (or globally)
}

// ---------------- CSR build ----------------
__global__ void k_zero() {
    int i = blockIdx.x * blockDim.x + threadIdx.x;
    if (i < NNODES) g_hist[i] = 0;
    if (i == 0) g_total = 0;
}
__global__ void k_hist(const int* __restrict__ dst) {
    int e = blockIdx.x * blockDim.x + threadIdx.x;
    if (e < NEDGES) atomicAdd(&g_hist[dst[e]], 1);
}
// block scan + atomic chunk reservation (no second scan kernel)
__global__ void __launch_bounds__(1024) k_scan1() {
    __shared__ int sh[1024];
    int i = blockIdx.x * 1024 + threadIdx.x;
    int h = (i < NNODES) ? g_hist[i] : 0;
    sh[threadIdx.x] = h;
    __syncthreads();
    #pragma unroll
    for (int ofs = 1; ofs < 1024; ofs <<= 1) {
        int v = (threadIdx.x >= ofs) ? sh[threadIdx.x - ofs] : 0;
        __syncthreads();
        sh[threadIdx.x] += v;
        __syncthreads();
    }
    if (i < NNODES) {
        g_offs[i] = sh[threadIdx.x] - h;
        g_dinv[i] = rsqrtf((float)(h + 1));
        g_cnt[i]  = 0;
    }
    if (threadIdx.x == 1023)
        g_boff[blockIdx.x] = atomicAdd(&g_total, sh[1023]);
}
__global__ void k_fill(const int* __restrict__ src, const int* __restrict__ dst) {
    int e = blockIdx.x * blockDim.x + threadIdx.x;
    if (e >= NEDGES) return;
    int s = src[e], d = dst[e];
    int pos = g_offs[d] + g_boff[d >> 10] + atomicAdd(&g_cnt[d], 1);
    g_csr_src[pos] = s;
}

// ---------------- GEMM1: h1h = (x @ W1) * dinv  (fp16 out) ----------------
// 256 threads, 128-row tile; thread = 8 rows x 4 strided cols.
// f32x2 packs over K (lo = even-k partial, hi = odd-k partial) -> zero broadcast MOVs.
#define XP 132
__global__ void __launch_bounds__(256, 2) k_gemm1(const float* __restrict__ x,
                                                  const float* __restrict__ W1) {
    __shared__ float xs[128 * XP];   // 67.6 KB, row-major: xs[r*XP + k]
    __shared__ float wt[HID * XP];   // 33.8 KB, transposed: wt[c*XP + k]
    const int tid  = threadIdx.x;
    const int row0 = blockIdx.x * 128;

    // load W1 transposed: W1[k][c] -> wt[c][k]
    #pragma unroll
    for (int i = 0; i < 32; i++) {
        int idx = tid + i * 256;          // [0, 8192)
        int k = idx >> 6, c = idx & 63;
        wt[c * XP + k] = W1[idx];
    }
    // load x tile (4096 float4), row-major pitched
    #pragma unroll
    for (int i = 0; i < 16; i++) {
        int f = tid + i * 256;
        int r = f >> 5;
        int o = (f & 31) << 2;
        float4 v = make_float4(0.f, 0.f, 0.f, 0.f);
        if (row0 + r < NNODES) v = *(const float4*)(x + (size_t)(row0 + r) * FIN + o);
        *(float4*)(xs + r * XP + o) = v;
    }
    __syncthreads();

    const int rp = tid >> 4;              // 0..15 -> rows rp*8..rp*8+7
    const int cg = tid & 15;              // cols cg + 16j, j=0..3
    const float* xr = xs + (rp * 8) * XP;

    u64 acc[8][4];
    #pragma unroll
    for (int r = 0; r < 8; r++)
        #pragma unroll
        for (int j = 0; j < 4; j++) acc[r][j] = 0ull;

    #pragma unroll 2
    for (int k = 0; k < FIN; k += 4) {
        W4 wv[4];
        #pragma unroll
        for (int j = 0; j < 4; j++)
            wv[j].v = *(const float4*)(wt + (cg + 16 * j) * XP + k);
        #pragma unroll
        for (int r = 0; r < 8; r++) {
            W4 xv;
            xv.v = *(const float4*)(xr + r * XP + k);
            #pragma unroll
            for (int j = 0; j < 4; j++) {
                acc[r][j] = ffma2(xv.u.lo, wv[j].u.lo, acc[r][j]);
                acc[r][j] = ffma2(xv.u.hi, wv[j].u.hi, acc[r][j]);
            }
        }
    }

    #pragma unroll
    for (int r = 0; r < 8; r++) {
        int row = row0 + rp * 8 + r;
        if (row >= NNODES) continue;
        float di = g_dinv[row];
        __half* hp = g_h1h + (size_t)row * HID;
        #pragma unroll
        for (int j = 0; j < 4; j++) {
            F2 a; a.u = acc[r][j];
            hp[cg + 16 * j] = __float2half_rn((a.f.x + a.f.y) * di);
        }
    }
}

// ---------------- agg1: agg1h[n] = relu((h1h[n] + sum h1h[src]) * dinv[n] + b1), fp16 ----------------
// 8 lanes per node; lane j owns 8 halves (16B).
__global__ void __launch_bounds__(256) k_agg1(const float* __restrict__ b1) {
    int t = blockIdx.x * 256 + threadIdx.x;
    int n = t >> 3;
    if (n >= NNODES) return;
    int j = t & 7;

    int p0, p1;
    node_range(n, p0, p1);

    float acc[8];
    {   // self-loop seed
        uint4 v = *(const uint4*)(g_h1h + (size_t)n * HID + j * 8);
        float2 f0 = h2tof2(v.x), f1 = h2tof2(v.y), f2 = h2tof2(v.z), f3 = h2tof2(v.w);
        acc[0] = f0.x; acc[1] = f0.y; acc[2] = f1.x; acc[3] = f1.y;
        acc[4] = f2.x; acc[5] = f2.y; acc[6] = f3.x; acc[7] = f3.y;
    }
    int p = p0;
    for (; p + 8 <= p1; p += 8) {
        int s[8];
        #pragma unroll
        for (int q = 0; q < 8; q++) s[q] = g_csr_src[p + q];
        uint4 v[8];
        #pragma unroll
        for (int q = 0; q < 8; q++)
            v[q] = *(const uint4*)(g_h1h + (size_t)s[q] * HID + j * 8);
        #pragma unroll
        for (int q = 0; q < 8; q++) {
            float2 f0 = h2tof2(v[q].x), f1 = h2tof2(v[q].y);
            float2 f2 = h2tof2(v[q].z), f3 = h2tof2(v[q].w);
            acc[0] += f0.x; acc[1] += f0.y; acc[2] += f1.x; acc[3] += f1.y;
            acc[4] += f2.x; acc[5] += f2.y; acc[6] += f3.x; acc[7] += f3.y;
        }
    }
    for (; p < p1; p++) {
        int s = g_csr_src[p];
        uint4 v = *(const uint4*)(g_h1h + (size_t)s * HID + j * 8);
        float2 f0 = h2tof2(v.x), f1 = h2tof2(v.y), f2 = h2tof2(v.z), f3 = h2tof2(v.w);
        acc[0] += f0.x; acc[1] += f0.y; acc[2] += f1.x; acc[3] += f1.y;
        acc[4] += f2.x; acc[5] += f2.y; acc[6] += f3.x; acc[7] += f3.y;
    }
    float di = g_dinv[n];
    float4 bb0 = *(const float4*)(b1 + j * 8);
    float4 bb1 = *(const float4*)(b1 + j * 8 + 4);
    float o0 = fmaxf(fmaf(acc[0], di, bb0.x), 0.f);
    float o1 = fmaxf(fmaf(acc[1], di, bb0.y), 0.f);
    float o2 = fmaxf(fmaf(acc[2], di, bb0.z), 0.f);
    float o3 = fmaxf(fmaf(acc[3], di, bb0.w), 0.f);
    float o4 = fmaxf(fmaf(acc[4], di, bb1.x), 0.f);
    float o5 = fmaxf(fmaf(acc[5], di, bb1.y), 0.f);
    float o6 = fmaxf(fmaf(acc[6], di, bb1.z), 0.f);
    float o7 = fmaxf(fmaf(acc[7], di, bb1.w), 0.f);
    uint4 st;
    __half2* sp = (__half2*)&st;
    sp[0] = __floats2half2_rn(o0, o1);
    sp[1] = __floats2half2_rn(o2, o3);
    sp[2] = __floats2half2_rn(o4, o5);
    sp[3] = __floats2half2_rn(o6, o7);
    *(uint4*)(g_agg1h + (size_t)n * HID + j * 8) = st;
}

// ---------------- GEMM2: h2h = (agg1h @ W2) * dinv  (fp16 in/out) ----------------
// 256 threads, 128-row tile; thread = 8 rows x 4 cols; col groups 10..15 idle.
#define XS2_PITCH 68
__global__ void __launch_bounds__(256, 2) k_gemm2(const float* __restrict__ W2) {
    __shared__ float xs[128 * XS2_PITCH];  // 34.8 KB
    __shared__ float ws[HID * 64];         // 16 KB (cols padded 40->64)
    const int tid  = threadIdx.x;
    const int row0 = blockIdx.x * 128;

    #pragma unroll
    for (int i = 0; i < 16; i++) {
        int idx = tid + i * 256;
        int k = idx >> 6, c = idx & 63;
        ws[idx] = (c < NCLS) ? W2[k * NCLS + c] : 0.0f;
    }
    #pragma unroll
    for (int i = 0; i < 4; i++) {
        int f = tid + i * 256;            // [0, 1024)
        int r = f >> 3;
        int c = f & 7;
        float v[8] = {0.f, 0.f, 0.f, 0.f, 0.f, 0.f, 0.f, 0.f};
        if (row0 + r < NNODES) {
            uint4 h = *(const uint4*)(g_agg1h + (size_t)(row0 + r) * HID + c * 8);
            float2 f0 = h2tof2(h.x), f1 = h2tof2(h.y), f2 = h2tof2(h.z), f3 = h2tof2(h.w);
            v[0] = f0.x; v[1] = f0.y; v[2] = f1.x; v[3] = f1.y;
            v[4] = f2.x; v[5] = f2.y; v[6] = f3.x; v[7] = f3.y;
        }
        float* xp = xs + r * XS2_PITCH + c * 8;
        *(float4*)(xp)     = make_float4(v[0], v[1], v[2], v[3]);
        *(float4*)(xp + 4) = make_float4(v[4], v[5], v[6], v[7]);
    }
    __syncthreads();

    const int rp = tid >> 4;
    const int cg = tid & 15;
    if (cg >= 10) return;
    const float* wcol = ws + cg * 4;
    const float* xr = xs + (rp * 8) * XS2_PITCH;

    u64 acc[8][2];
    #pragma unroll
    for (int r = 0; r < 8; r++) { acc[r][0] = 0ull; acc[r][1] = 0ull; }

    #pragma unroll 2
    for (int k = 0; k < HID; k += 4) {
        float4 xa[8];
        #pragma unroll
        for (int r = 0; r < 8; r++)
            xa[r] = *(const float4*)(xr + r * XS2_PITCH + k);
        #pragma unroll
        for (int kk = 0; kk < 4; kk++) {
            W4 w;
            w.v = *(const float4*)(wcol + (k + kk) * 64);
            #pragma unroll
            for (int r = 0; r < 8; r++) {
                u64 xv = pack2((&xa[r].x)[kk]);
                acc[r][0] = ffma2(w.u.lo, xv, acc[r][0]);
                acc[r][1] = ffma2(w.u.hi, xv, acc[r][1]);
            }
        }
    }

    #pragma unroll
    for (int r = 0; r < 8; r++) {
        int row = row0 + rp * 8 + r;
        if (row >= NNODES) continue;
        float di = g_dinv[row];
        F2 a0, a1;
        a0.u = acc[r][0]; a1.u = acc[r][1];
        uint2 st;
        __half2* sp = (__half2*)&st;
        sp[0] = __floats2half2_rn(a0.f.x * di, a0.f.y * di);
        sp[1] = __floats2half2_rn(a1.f.x * di, a1.f.y * di);
        *(uint2*)(g_h2h + (size_t)row * NCLS + cg * 4) = st;
    }
}

// ---------------- agg2: out[n] = (h2h[n] + sum h2h[src]) * dinv[n] + b2 ----------------
// 5 lanes per node; lane j owns 8 halves (16B).
__global__ void __launch_bounds__(256) k_agg2(const float* __restrict__ b2,
                                              float* __restrict__ out) {
    int t = blockIdx.x * 256 + threadIdx.x;
    int n = t / 5;
    if (n >= NNODES) return;
    int j = t - n * 5;

    int p0, p1;
    node_range(n, p0, p1);

    float acc[8];
    {
        uint4 v = *(const uint4*)(g_h2h + (size_t)n * NCLS + j * 8);
        float2 f0 = h2tof2(v.x), f1 = h2tof2(v.y), f2 = h2tof2(v.z), f3 = h2tof2(v.w);
        acc[0] = f0.x; acc[1] = f0.y; acc[2] = f1.x; acc[3] = f1.y;
        acc[4] = f2.x; acc[5] = f2.y; acc[6] = f3.x; acc[7] = f3.y;
    }
    int p = p0;
    for (; p + 8 <= p1; p += 8) {
        int s[8];
        #pragma unroll
        for (int q = 0; q < 8; q++) s[q] = g_csr_src[p + q];
        uint4 v[8];
        #pragma unroll
        for (int q = 0; q < 8; q++)
            v[q] = *(const uint4*)(g_h2h + (size_t)s[q] * NCLS + j * 8);
        #pragma unroll
        for (int q = 0; q < 8; q++) {
            float2 f0 = h2tof2(v[q].x), f1 = h2tof2(v[q].y);
            float2 f2 = h2tof2(v[q].z), f3 = h2tof2(v[q].w);
            acc[0] += f0.x; acc[1] += f0.y; acc[2] += f1.x; acc[3] += f1.y;
            acc[4] += f2.x; acc[5] += f2.y; acc[6] += f3.x; acc[7] += f3.y;
        }
    }
    for (; p < p1; p++) {
        int s = g_csr_src[p];
        uint4 v = *(const uint4*)(g_h2h + (size_t)s * NCLS + j * 8);
        float2 f0 = h2tof2(v.x), f1 = h2tof2(v.y), f2 = h2tof2(v.z), f3 = h2tof2(v.w);
        acc[0] += f0.x; acc[1] += f0.y; acc[2] += f1.x; acc[3] += f1.y;
        acc[4] += f2.x; acc[5] += f2.y; acc[6] += f3.x; acc[7] += f3.y;
    }
    float di = g_dinv[n];
    float4 bb0 = *(const float4*)(b2 + j * 8);
    float4 bb1 = *(const float4*)(b2 + j * 8 + 4);
    float* op = out + (size_t)n * NCLS + j * 8;
    *(float4*)(op)     = make_float4(fmaf(acc[0], di, bb0.x), fmaf(acc[1], di, bb0.y),
                                     fmaf(acc[2], di, bb0.z), fmaf(acc[3], di, bb0.w));
    *(float4*)(op + 4) = make_float4(fmaf(acc[4], di, bb1.x), fmaf(acc[5], di, bb1.y),
                                     fmaf(acc[6], di, bb1.z), fmaf(acc[7], di, bb1.w));
}

// ---------------- launch ----------------
extern "C" void kernel_launch(void* const* d_in, const int* in_sizes, int n_in,
                              void* d_out, int out_size) {
    const float* x   = (const float*)d_in[0];
    const int*   ei  = (const int*)d_in[1];
    const float* W1  = (const float*)d_in[2];
    const float* b1  = (const float*)d_in[3];
    const float* W2  = (const float*)d_in[4];
    const float* b2  = (const float*)d_in[5];
    float* out = (float*)d_out;

    const int* src = ei;
    const int* dst = ei + NEDGES;

    // CSR build + dinv (scan2 folded into scan1 via atomic chunk reservation)
    k_zero<<<(NNODES + 255) / 256, 256>>>();
    k_hist<<<(NEDGES + 255) / 256, 256>>>(dst);
    k_scan1<<<SCAN_BLOCKS, 1024>>>();
    k_fill<<<(NEDGES + 255) / 256, 256>>>(src, dst);

    // layer 1
    k_gemm1<<<(NNODES + 127) / 128, 256>>>(x, W1);
    k_agg1<<<(NNODES * 8 + 255) / 256, 256>>>(b1);

    // layer 2
    k_gemm2<<<(NNODES + 127) / 128, 256>>>(W2);
    k_agg2<<<(NNODES * 5 + 255) / 256, 256>>>(b2, out);
}

// round 14
// speedup vs baseline: 1.3435x; 1.0136x over previous
#include <cuda_runtime.h>
#include <cuda_fp16.h>
#include <cstdint>

#define NNODES 100000
#define NEDGES 1600000
#define FIN    128
#define HID    64
#define NCLS   40

#define SCAN_BLOCKS 98   // 98 * 1024 >= NNODES

// ---------------- device scratch (allocation-free) ----------------
__device__ int    g_hist[NNODES];
__device__ int    g_rank[NEDGES];          // within-node arrival rank of each edge
__device__ int    g_offs[NNODES];          // block-local exclusive offsets
__device__ int    g_boff[SCAN_BLOCKS];     // per-block base in edge array (atomic chunk)
__device__ int    g_total;                 // chunk-reservation counter
__device__ int    g_csr_src[NEDGES];
__device__ float  g_dinv[NNODES];
__device__ __half g_h1h[(size_t)NNODES * HID];    // (x @ W1) * dinv[row], fp16
__device__ __half g_agg1h[(size_t)NNODES * HID];  // relu(layer-1 agg), fp16
__device__ __half g_h2h[(size_t)NNODES * NCLS];   // (relu_agg1 @ W2) * dinv[row], fp16

// ---------------- helpers ----------------
typedef unsigned long long u64;
__device__ __forceinline__ u64 ffma2(u64 a, u64 b, u64 c) {
    u64 d;
    asm("fma.rn.f32x2 %0, %1, %2, %3;" : "=l"(d) : "l"(a), "l"(b), "l"(c));
    return d;
}
__device__ __forceinline__ u64 pack2(float x) {
    u64 d;
    asm("mov.b64 %0, {%1, %1};" : "=l"(d) : "f"(x));
    return d;
}
union F2 { u64 u; float2 f; };
union W4 { float4 v; struct { u64 lo, hi; } u; };

__device__ __forceinline__ float2 h2tof2(uint32_t h) {
    __half2 hh = *reinterpret_cast<__half2*>(&h);
    return __half22float2(hh);
}

// global CSR range for node n
__device__ __forceinline__ void node_range(int n, int& p0, int& p1) {
    p0 = g_offs[n] + g_boff[n >> 10];
    int m = n + 1;
    if ((m >> 10) == (n >> 10) && m < NNODES)
        p1 = g_offs[m] + g_boff[m >> 10];
    else
        p1 = p0 + g_hist[n];   // last node in block (or globally)
}

// ---------------- CSR build ----------------
__global__ void k_zero() {
    int i = blockIdx.x * blockDim.x + threadIdx.x;
    if (i < NNODES) g_hist[i] = 0;
    if (i == 0) g_total = 0;
}
// histogram that also records each edge's within-node rank (coalesced store)
__global__ void k_hist(const int* __restrict__ dst) {
    int e = blockIdx.x * blockDim.x + threadIdx.x;
    if (e < NEDGES) g_rank[e] = atomicAdd(&g_hist[dst[e]], 1);
}
// block scan + atomic chunk reservation
__global__ void __launch_bounds__(1024) k_scan1() {
    __shared__ int sh[1024];
    int i = blockIdx.x * 1024 + threadIdx.x;
    int h = (i < NNODES) ? g_hist[i] : 0;
    sh[threadIdx.x] = h;
    __syncthreads();
    #pragma unroll
    for (int ofs = 1; ofs < 1024; ofs <<= 1) {
        int v = (threadIdx.x >= ofs) ? sh[threadIdx.x - ofs] : 0;
        __syncthreads();
        sh[threadIdx.x] += v;
        __syncthreads();
    }
    if (i < NNODES) {
        g_offs[i] = sh[threadIdx.x] - h;
        g_dinv[i] = rsqrtf((float)(h + 1));
    }
    if (threadIdx.x == 1023)
        g_boff[blockIdx.x] = atomicAdd(&g_total, sh[1023]);
}
// atomic-free scatter: position fully determined by precomputed rank
__global__ void k_fill(const int* __restrict__ src, const int* __restrict__ dst) {
    int e = blockIdx.x * blockDim.x + threadIdx.x;
    if (e >= NEDGES) return;
    int d = dst[e];
    int pos = g_offs[d] + g_boff[d >> 10] + g_rank[e];
    g_csr_src[pos] = src[e];
}

// ---------------- GEMM1: h1h = (x @ W1) * dinv  (fp16 out) ----------------
// 256 threads, 128-row tile; thread = 8 rows x 4 strided cols; f32x2 packed over K.
#define XP 132
__global__ void __launch_bounds__(256, 2) k_gemm1(const float* __restrict__ x,
                                                  const float* __restrict__ W1) {
    __shared__ float xs[128 * XP];   // 67.6 KB, row-major: xs[r*XP + k]
    __shared__ float wt[HID * XP];   // 33.8 KB, transposed: wt[c*XP + k]
    const int tid  = threadIdx.x;
    const int row0 = blockIdx.x * 128;

    // load W1 transposed: W1[k][c] -> wt[c][k]
    #pragma unroll
    for (int i = 0; i < 32; i++) {
        int idx = tid + i * 256;          // [0, 8192)
        int k = idx >> 6, c = idx & 63;
        wt[c * XP + k] = W1[idx];
    }
    // load x tile (4096 float4), row-major pitched
    #pragma unroll
    for (int i = 0; i < 16; i++) {
        int f = tid + i * 256;
        int r = f >> 5;
        int o = (f & 31) << 2;
        float4 v = make_float4(0.f, 0.f, 0.f, 0.f);
        if (row0 + r < NNODES) v = *(const float4*)(x + (size_t)(row0 + r) * FIN + o);
        *(float4*)(xs + r * XP + o) = v;
    }
    __syncthreads();

    const int rp = tid >> 4;              // 0..15 -> rows rp*8..rp*8+7
    const int cg = tid & 15;              // cols cg + 16j, j=0..3
    const float* xr = xs + (rp * 8) * XP;

    u64 acc[8][4];
    #pragma unroll
    for (int r = 0; r < 8; r++)
        #pragma unroll
        for (int j = 0; j < 4; j++) acc[r][j] = 0ull;

    #pragma unroll 2
    for (int k = 0; k < FIN; k += 4) {
        W4 wv[4];
        #pragma unroll
        for (int j = 0; j < 4; j++)
            wv[j].v = *(const float4*)(wt + (cg + 16 * j) * XP + k);
        #pragma unroll
        for (int r = 0; r < 8; r++) {
            W4 xv;
            xv.v = *(const float4*)(xr + r * XP + k);
            #pragma unroll
            for (int j = 0; j < 4; j++) {
                acc[r][j] = ffma2(xv.u.lo, wv[j].u.lo, acc[r][j]);
                acc[r][j] = ffma2(xv.u.hi, wv[j].u.hi, acc[r][j]);
            }
        }
    }

    #pragma unroll
    for (int r = 0; r < 8; r++) {
        int row = row0 + rp * 8 + r;
        if (row >= NNODES) continue;
        float di = g_dinv[row];
        __half* hp = g_h1h + (size_t)row * HID;
        #pragma unroll
        for (int j = 0; j < 4; j++) {
            F2 a; a.u = acc[r][j];
            hp[cg + 16 * j] = __float2half_rn((a.f.x + a.f.y) * di);
        }
    }
}

// ---------------- agg1: agg1h[n] = relu((h1h[n] + sum h1h[src]) * dinv[n] + b1), fp16 ----------------
// 8 lanes per node; lane j owns 8 halves (16B).
__global__ void __launch_bounds__(256) k_agg1(const float* __restrict__ b1) {
    int t = blockIdx.x * 256 + threadIdx.x;
    int n = t >> 3;
    if (n >= NNODES) return;
    int j = t & 7;

    int p0, p1;
    node_range(n, p0, p1);

    float acc[8];
    {   // self-loop seed
        uint4 v = *(const uint4*)(g_h1h + (size_t)n * HID + j * 8);
        float2 f0 = h2tof2(v.x), f1 = h2tof2(v.y), f2 = h2tof2(v.z), f3 = h2tof2(v.w);
        acc[0] = f0.x; acc[1] = f0.y; acc[2] = f1.x; acc[3] = f1.y;
        acc[4] = f2.x; acc[5] = f2.y; acc[6] = f3.x; acc[7] = f3.y;
    }
    int p = p0;
    for (; p + 8 <= p1; p += 8) {
        int s[8];
        #pragma unroll
        for (int q = 0; q < 8; q++) s[q] = g_csr_src[p + q];
        uint4 v[8];
        #pragma unroll
        for (int q = 0; q < 8; q++)
            v[q] = *(const uint4*)(g_h1h + (size_t)s[q] * HID + j * 8);
        #pragma unroll
        for (int q = 0; q < 8; q++) {
            float2 f0 = h2tof2(v[q].x), f1 = h2tof2(v[q].y);
            float2 f2 = h2tof2(v[q].z), f3 = h2tof2(v[q].w);
            acc[0] += f0.x; acc[1] += f0.y; acc[2] += f1.x; acc[3] += f1.y;
            acc[4] += f2.x; acc[5] += f2.y; acc[6] += f3.x; acc[7] += f3.y;
        }
    }
    for (; p < p1; p++) {
        int s = g_csr_src[p];
        uint4 v = *(const uint4*)(g_h1h + (size_t)s * HID + j * 8);
        float2 f0 = h2tof2(v.x), f1 = h2tof2(v.y), f2 = h2tof2(v.z), f3 = h2tof2(v.w);
        acc[0] += f0.x; acc[1] += f0.y; acc[2] += f1.x; acc[3] += f1.y;
        acc[4] += f2.x; acc[5] += f2.y; acc[6] += f3.x; acc[7] += f3.y;
    }
    float di = g_dinv[n];
    float4 bb0 = *(const float4*)(b1 + j * 8);
    float4 bb1 = *(const float4*)(b1 + j * 8 + 4);
    float o0 = fmaxf(fmaf(acc[0], di, bb0.x), 0.f);
    float o1 = fmaxf(fmaf(acc[1], di, bb0.y), 0.f);
    float o2 = fmaxf(fmaf(acc[2], di, bb0.z), 0.f);
    float o3 = fmaxf(fmaf(acc[3], di, bb0.w), 0.f);
    float o4 = fmaxf(fmaf(acc[4], di, bb1.x), 0.f);
    float o5 = fmaxf(fmaf(acc[5], di, bb1.y), 0.f);
    float o6 = fmaxf(fmaf(acc[6], di, bb1.z), 0.f);
    float o7 = fmaxf(fmaf(acc[7], di, bb1.w), 0.f);
    uint4 st;
    __half2* sp = (__half2*)&st;
    sp[0] = __floats2half2_rn(o0, o1);
    sp[1] = __floats2half2_rn(o2, o3);
    sp[2] = __floats2half2_rn(o4, o5);
    sp[3] = __floats2half2_rn(o6, o7);
    *(uint4*)(g_agg1h + (size_t)n * HID + j * 8) = st;
}

// ---------------- GEMM2: h2h = (agg1h @ W2) * dinv  (fp16 in/out) ----------------
#define XS2_PITCH 68
__global__ void __launch_bounds__(256, 2) k_gemm2(const float* __restrict__ W2) {
    __shared__ float xs[128 * XS2_PITCH];  // 34.8 KB
    __shared__ float ws[HID * 64];         // 16 KB (cols padded 40->64)
    const int tid  = threadIdx.x;
    const int row0 = blockIdx.x * 128;

    #pragma unroll
    for (int i = 0; i < 16; i++) {
        int idx = tid + i * 256;
        int k = idx >> 6, c = idx & 63;
        ws[idx] = (c < NCLS) ? W2[k * NCLS + c] : 0.0f;
    }
    #pragma unroll
    for (int i = 0; i < 4; i++) {
        int f = tid + i * 256;            // [0, 1024)
        int r = f >> 3;
        int c = f & 7;
        float v[8] = {0.f, 0.f, 0.f, 0.f, 0.f, 0.f, 0.f, 0.f};
        if (row0 + r < NNODES) {
            uint4 h = *(const uint4*)(g_agg1h + (size_t)(row0 + r) * HID + c * 8);
            float2 f0 = h2tof2(h.x), f1 = h2tof2(h.y), f2 = h2tof2(h.z), f3 = h2tof2(h.w);
            v[0] = f0.x; v[1] = f0.y; v[2] = f1.x; v[3] = f1.y;
            v[4] = f2.x; v[5] = f2.y; v[6] = f3.x; v[7] = f3.y;
        }
        float* xp = xs + r * XS2_PITCH + c * 8;
        *(float4*)(xp)     = make_float4(v[0], v[1], v[2], v[3]);
        *(float4*)(xp + 4) = make_float4(v[4], v[5], v[6], v[7]);
    }
    __syncthreads();

    const int rp = tid >> 4;
    const int cg = tid & 15;
    if (cg >= 10) return;
    const float* wcol = ws + cg * 4;
    const float* xr = xs + (rp * 8) * XS2_PITCH;

    u64 acc[8][2];
    #pragma unroll
    for (int r = 0; r < 8; r++) { acc[r][0] = 0ull; acc[r][1] = 0ull; }

    #pragma unroll 2
    for (int k = 0; k < HID; k += 4) {
        float4 xa[8];
        #pragma unroll
        for (int r = 0; r < 8; r++)
            xa[r] = *(const float4*)(xr + r * XS2_PITCH + k);
        #pragma unroll
        for (int kk = 0; kk < 4; kk++) {
            W4 w;
            w.v = *(const float4*)(wcol + (k + kk) * 64);
            #pragma unroll
            for (int r = 0; r < 8; r++) {
                u64 xv = pack2((&xa[r].x)[kk]);
                acc[r][0] = ffma2(w.u.lo, xv, acc[r][0]);
                acc[r][1] = ffma2(w.u.hi, xv, acc[r][1]);
            }
        }
    }

    #pragma unroll
    for (int r = 0; r < 8; r++) {
        int row = row0 + rp * 8 + r;
        if (row >= NNODES) continue;
        float di = g_dinv[row];
        F2 a0, a1;
        a0.u = acc[r][0]; a1.u = acc[r][1];
        uint2 st;
        __half2* sp = (__half2*)&st;
        sp[0] = __floats2half2_rn(a0.f.x * di, a0.f.y * di);
        sp[1] = __floats2half2_rn(a1.f.x * di, a1.f.y * di);
        *(uint2*)(g_h2h + (size_t)row * NCLS + cg * 4) = st;
    }
}

// ---------------- agg2: out[n] = (h2h[n] + sum h2h[src]) * dinv[n] + b2 ----------------
// 5 lanes per node; lane j owns 8 halves (16B).
__global__ void __launch_bounds__(256) k_agg2(const float* __restrict__ b2,
                                              float* __restrict__ out) {
    int t = blockIdx.x * 256 + threadIdx.x;
    int n = t / 5;
    if (n >= NNODES) return;
    int j = t - n * 5;

    int p0, p1;
    node_range(n, p0, p1);

    float acc[8];
    {
        uint4 v = *(const uint4*)(g_h2h + (size_t)n * NCLS + j * 8);
        float2 f0 = h2tof2(v.x), f1 = h2tof2(v.y), f2 = h2tof2(v.z), f3 = h2tof2(v.w);
        acc[0] = f0.x; acc[1] = f0.y; acc[2] = f1.x; acc[3] = f1.y;
        acc[4] = f2.x; acc[5] = f2.y; acc[6] = f3.x; acc[7] = f3.y;
    }
    int p = p0;
    for (; p + 8 <= p1; p += 8) {
        int s[8];
        #pragma unroll
        for (int q = 0; q < 8; q++) s[q] = g_csr_src[p + q];
        uint4 v[8];
        #pragma unroll
        for (int q = 0; q < 8; q++)
            v[q] = *(const uint4*)(g_h2h + (size_t)s[q] * NCLS + j * 8);
        #pragma unroll
        for (int q = 0; q < 8; q++) {
            float2 f0 = h2tof2(v[q].x), f1 = h2tof2(v[q].y);
            float2 f2 = h2tof2(v[q].z), f3 = h2tof2(v[q].w);
            acc[0] += f0.x; acc[1] += f0.y; acc[2] += f1.x; acc[3] += f1.y;
            acc[4] += f2.x; acc[5] += f2.y; acc[6] += f3.x; acc[7] += f3.y;
        }
    }
    for (; p < p1; p++) {
        int s = g_csr_src[p];
        uint4 v = *(const uint4*)(g_h2h + (size_t)s * NCLS + j * 8);
        float2 f0 = h2tof2(v.x), f1 = h2tof2(v.y), f2 = h2tof2(v.z), f3 = h2tof2(v.w);
        acc[0] += f0.x; acc[1] += f0.y; acc[2] += f1.x; acc[3] += f1.y;
        acc[4] += f2.x; acc[5] += f2.y; acc[6] += f3.x; acc[7] += f3.y;
    }
    float di = g_dinv[n];
    float4 bb0 = *(const float4*)(b2 + j * 8);
    float4 bb1 = *(const float4*)(b2 + j * 8 + 4);
    float* op = out + (size_t)n * NCLS + j * 8;
    *(float4*)(op)     = make_float4(fmaf(acc[0], di, bb0.x), fmaf(acc[1], di, bb0.y),
                                     fmaf(acc[2], di, bb0.z), fmaf(acc[3], di, bb0.w));
    *(float4*)(op + 4) = make_float4(fmaf(acc[4], di, bb1.x), fmaf(acc[5], di, bb1.y),
                                     fmaf(acc[6], di, bb1.z), fmaf(acc[7], di, bb1.w));
}

// ---------------- launch ----------------
extern "C" void kernel_launch(void* const* d_in, const int* in_sizes, int n_in,
                              void* d_out, int out_size) {
    const float* x   = (const float*)d_in[0];
    const int*   ei  = (const int*)d_in[1];
    const float* W1  = (const float*)d_in[2];
    const float* b1  = (const float*)d_in[3];
    const float* W2  = (const float*)d_in[4];
    const float* b2  = (const float*)d_in[5];
    float* out = (float*)d_out;

    const int* src = ei;
    const int* dst = ei + NEDGES;

    // CSR build + dinv (rank-based fill: no atomics in fill)
    k_zero<<<(NNODES + 255) / 256, 256>>>();
    k_hist<<<(NEDGES + 255) / 256, 256>>>(dst);
    k_scan1<<<SCAN_BLOCKS, 1024>>>();
    k_fill<<<(NEDGES + 255) / 256, 256>>>(src, dst);

    // layer 1
    k_gemm1<<<(NNODES + 127) / 128, 256>>>(x, W1);
    k_agg1<<<(NNODES * 8 + 255) / 256, 256>>>(b1);

    // layer 2
    k_gemm2<<<(NNODES + 127) / 128, 256>>>(W2);
    k_agg2<<<(NNODES * 5 + 255) / 256, 256>>>(b2, out);
}